// round 13
// baseline (speedup 1.0000x reference)
#include <cuda_runtime.h>
#include <cuda_fp16.h>
#include <cstdint>

#define NN 50000
#define NE 800000
#define F 64
#define KF 256    // F * K
#define OUTF 256
#define NB 49     // scan blocks of 1024 nodes
#define KW (KF / 2)   // 128 half2 words per Xt row

// Scratch (device globals: allocation-free rule)
__device__ int   g_degi[NN];
__device__ int   g_rowptr[NN + 1];
__device__ int   g_cursor[NN];
__device__ int   g_csrc[NE];
__device__ int   g_psum[NB];
__device__ __align__(16) float    g_dsqrt[NN];
__device__ __align__(16) uint32_t g_scaled_a[NN * F / 2];   // half2 packed
__device__ __align__(16) uint32_t g_scaled_b[NN * F / 2];
__device__ __align__(16) float    g_Xt[(size_t)NN * KF];    // fp32 recurrence spine
__device__ __align__(16) uint32_t g_Xt16[(size_t)NN * KW];  // half2 words for GEMM A
__device__ __align__(16) uint32_t g_Wt16[OUTF * KW];        // half2, transposed [n][kw]

__global__ void k_zero() {
    int i = blockIdx.x * blockDim.x + threadIdx.x;
    if (i < NN) g_degi[i] = 0;
}

// 4 edges per thread: 4 independent atomic chains.
__global__ void k_deg(const int* __restrict__ dst) {
    int q = blockIdx.x * blockDim.x + threadIdx.x;
    if (q >= NE / 4) return;
    int4 dv = ((const int4*)dst)[q];
    atomicAdd(&g_degi[dv.x], 1);
    atomicAdd(&g_degi[dv.y], 1);
    atomicAdd(&g_degi[dv.z], 1);
    atomicAdd(&g_degi[dv.w], 1);
}

// ---- parallel scan (2 kernels: partials, then fused top-scan + fill) --------
__global__ __launch_bounds__(256) void k_scan_part() {
    __shared__ int s[256];
    int t = threadIdx.x, b = blockIdx.x;
    int base = b * 1024 + t * 4;
    int sum = 0;
    #pragma unroll
    for (int j = 0; j < 4; j++) {
        int i = base + j;
        if (i < NN) sum += g_degi[i];
    }
    s[t] = sum;
    __syncthreads();
    for (int off = 128; off > 0; off >>= 1) {
        if (t < off) s[t] += s[t + off];
        __syncthreads();
    }
    if (t == 0) g_psum[b] = s[0];
}

__global__ __launch_bounds__(256) void k_scan_fill() {
    __shared__ int s[256];
    __shared__ int tops[64];
    int t = threadIdx.x, b = blockIdx.x;

    if (t < 64) tops[t] = (t < NB) ? g_psum[t] : 0;
    __syncthreads();
    for (int off = 1; off < 64; off <<= 1) {
        int u = (t >= off && t < 64) ? tops[t - off] : 0;
        __syncthreads();
        if (t < 64) tops[t] += u;
        __syncthreads();
    }
    int blockoff = (b == 0) ? 0 : tops[b - 1];
    if (b == 0 && t == 0) g_rowptr[NN] = NE;

    int base = b * 1024 + t * 4;
    int d[4];
    int sum = 0;
    #pragma unroll
    for (int j = 0; j < 4; j++) {
        int i = base + j;
        d[j] = (i < NN) ? g_degi[i] : 0;
        sum += d[j];
    }
    s[t] = sum;
    __syncthreads();
    for (int off = 1; off < 256; off <<= 1) {
        int u = (t >= off) ? s[t - off] : 0;
        __syncthreads();
        s[t] += u;
        __syncthreads();
    }
    int off = blockoff + s[t] - sum;   // exclusive
    #pragma unroll
    for (int j = 0; j < 4; j++) {
        int i = base + j;
        if (i < NN) {
            g_rowptr[i] = off;
            g_cursor[i] = off;
            off += d[j];
        }
    }
}
// -----------------------------------------------------------------------------

// 8 edges per thread: 8 independent ATOMG->STG chains for MLP.
__global__ void k_fill(const int* __restrict__ src, const int* __restrict__ dst) {
    int q = blockIdx.x * blockDim.x + threadIdx.x;     // octet index
    if (q >= NE / 8) return;
    int4 dv0 = ((const int4*)dst)[2 * q];
    int4 dv1 = ((const int4*)dst)[2 * q + 1];
    int4 sv0 = ((const int4*)src)[2 * q];
    int4 sv1 = ((const int4*)src)[2 * q + 1];
    int p0 = atomicAdd(&g_cursor[dv0.x], 1);
    int p1 = atomicAdd(&g_cursor[dv0.y], 1);
    int p2 = atomicAdd(&g_cursor[dv0.z], 1);
    int p3 = atomicAdd(&g_cursor[dv0.w], 1);
    int p4 = atomicAdd(&g_cursor[dv1.x], 1);
    int p5 = atomicAdd(&g_cursor[dv1.y], 1);
    int p6 = atomicAdd(&g_cursor[dv1.z], 1);
    int p7 = atomicAdd(&g_cursor[dv1.w], 1);
    g_csrc[p0] = sv0.x;
    g_csrc[p1] = sv0.y;
    g_csrc[p2] = sv0.z;
    g_csrc[p3] = sv0.w;
    g_csrc[p4] = sv1.x;
    g_csrc[p5] = sv1.y;
    g_csrc[p6] = sv1.z;
    g_csrc[p7] = sv1.w;
}

__device__ __forceinline__ uint32_t pack_h2(float a, float b) {
    __half2 h = __floats2half2_rn(a, b);
    return *(uint32_t*)&h;
}

// Fused prep: node features (d^-1/2, X0 fp32+fp16, scaled fp16) AND W transpose.
__global__ void k_prep(const float* __restrict__ x, const float* __restrict__ W) {
    int t = blockIdx.x * blockDim.x + threadIdx.x;
    if (t < NN * 16) {
        int i = t >> 4, c = t & 15;
        float ds = rsqrtf((float)max(g_degi[i], 1));
        if (c == 0) g_dsqrt[i] = ds;
        float4 v = ((const float4*)x)[(size_t)i * 16 + c];
        ((float4*)(g_Xt + (size_t)i * KF))[c] = v;   // X0 into block 0
        uint2 xw = make_uint2(pack_h2(v.x, v.y), pack_h2(v.z, v.w));
        ((uint2*)(g_Xt16 + (size_t)i * KW))[c] = xw;
        uint2 s = make_uint2(pack_h2(v.x * ds, v.y * ds), pack_h2(v.z * ds, v.w * ds));
        ((uint2*)g_scaled_a)[(size_t)i * 16 + c] = s;
    } else {
        int i = t - NN * 16;
        if (i < OUTF * KW) {
            int n = i / KW, w = i % KW;
            int k = 2 * w;
            g_Wt16[(size_t)n * KW + w] =
                pack_h2(W[(size_t)k * OUTF + n], W[(size_t)(k + 1) * OUTF + n]);
        }
    }
}

// Gather-based Laplacian (fp16 inputs, fp32 math) + fused Chebyshev recurrence.
__global__ __launch_bounds__(256) void k_gather_cheb(const float* __restrict__ lambda_max,
                                                     int step, int ping) {
    int t = blockIdx.x * blockDim.x + threadIdx.x;
    if (t >= NN * 16) return;
    int i = t >> 4, c = t & 15;
    const uint2* in = (const uint2*)(ping ? g_scaled_b : g_scaled_a);
    uint2* outb = (uint2*)(ping ? g_scaled_a : g_scaled_b);

    int lo = g_rowptr[i], hi = g_rowptr[i + 1];
    float4 a0 = make_float4(0.f, 0.f, 0.f, 0.f);
    float4 a1 = make_float4(0.f, 0.f, 0.f, 0.f);
    float4 a2 = make_float4(0.f, 0.f, 0.f, 0.f);
    float4 a3 = make_float4(0.f, 0.f, 0.f, 0.f);

    auto acc = [&](float4& a, uint2 v) {
        float2 lo2 = __half22float2(*(__half2*)&v.x);
        float2 hi2 = __half22float2(*(__half2*)&v.y);
        a.x += lo2.x; a.y += lo2.y; a.z += hi2.x; a.w += hi2.y;
    };

    int j = lo;
    for (; j + 3 < hi; j += 4) {
        int s0 = __ldg(&g_csrc[j]);
        int s1 = __ldg(&g_csrc[j + 1]);
        int s2 = __ldg(&g_csrc[j + 2]);
        int s3 = __ldg(&g_csrc[j + 3]);
        uint2 v0 = in[(size_t)s0 * 16 + c];
        uint2 v1 = in[(size_t)s1 * 16 + c];
        uint2 v2 = in[(size_t)s2 * 16 + c];
        uint2 v3 = in[(size_t)s3 * 16 + c];
        acc(a0, v0); acc(a1, v1); acc(a2, v2); acc(a3, v3);
    }
    for (; j < hi; j++) {
        int s0 = __ldg(&g_csrc[j]);
        acc(a0, in[(size_t)s0 * 16 + c]);
    }
    float ds = g_dsqrt[i];
    float4 L = make_float4((a0.x + a1.x + a2.x + a3.x) * ds,
                           (a0.y + a1.y + a2.y + a3.y) * ds,
                           (a0.z + a1.z + a2.z + a3.z) * ds,
                           (a0.w + a1.w + a2.w + a3.w) * ds);

    float rn = 2.0f / lambda_max[0];
    float4* XtRow = (float4*)(g_Xt + (size_t)i * KF);
    float4 xp = XtRow[(step - 1) * 16 + c];
    float4 xn;
    if (step == 1) {
        float cL = -rn, cP = rn - 1.0f;
        xn = make_float4(cL * L.x + cP * xp.x, cL * L.y + cP * xp.y,
                         cL * L.z + cP * xp.z, cL * L.w + cP * xp.w);
    } else {
        float4 xpp = XtRow[(step - 2) * 16 + c];
        float cL = -2.0f * rn, cP = 2.0f * (rn - 1.0f);
        xn = make_float4(cL * L.x + cP * xp.x - xpp.x, cL * L.y + cP * xp.y - xpp.y,
                         cL * L.z + cP * xp.z - xpp.z, cL * L.w + cP * xp.w - xpp.w);
    }
    XtRow[step * 16 + c] = xn;
    uint2 xw = make_uint2(pack_h2(xn.x, xn.y), pack_h2(xn.z, xn.w));
    ((uint2*)(g_Xt16 + (size_t)i * KW))[step * 16 + c] = xw;
    uint2 s = make_uint2(pack_h2(xn.x * ds, xn.y * ds), pack_h2(xn.z * ds, xn.w * ds));
    outb[(size_t)i * 16 + c] = s;
}

// ---------------------------------------------------------------------------
// FP16 tensor-core GEMM with ldmatrix fragment loads.
// 128x128 block tile, BKW=16 half2-words per stage, 2-stage cp.async,
// static 40KB smem, 256 threads (8 warps, 4x2), warp tile 32x64,
// mma.sync.m16n8k16.f16. PITCH 20: conflict-free for LDSM and cp.async.
// B fragments loaded pair-wise and consumed immediately -> fewer live regs,
// __launch_bounds__(256, 3) targets 3 CTAs/SM (was 2).
// ---------------------------------------------------------------------------
#define BKW 16
#define PITCH 20
#define STGW (128 * PITCH)   // words per stage

__device__ __forceinline__ void cpa16(uint32_t dst_smem, const void* src, int sz) {
    asm volatile("cp.async.cg.shared.global [%0], [%1], 16, %2;"
                 :: "r"(dst_smem), "l"(src), "r"(sz));
}

__device__ __forceinline__ void ldsm4(uint32_t& r0, uint32_t& r1, uint32_t& r2,
                                      uint32_t& r3, uint32_t addr) {
    asm volatile("ldmatrix.sync.aligned.m8n8.x4.shared.b16 {%0,%1,%2,%3}, [%4];"
                 : "=r"(r0), "=r"(r1), "=r"(r2), "=r"(r3) : "r"(addr));
}

__device__ __forceinline__ void mma16(float* c, const uint32_t* a,
                                      uint32_t b0, uint32_t b1) {
    asm volatile(
        "mma.sync.aligned.m16n8k16.row.col.f32.f16.f16.f32 "
        "{%0,%1,%2,%3}, {%4,%5,%6,%7}, {%8,%9}, {%0,%1,%2,%3};"
        : "+f"(c[0]), "+f"(c[1]), "+f"(c[2]), "+f"(c[3])
        : "r"(a[0]), "r"(a[1]), "r"(a[2]), "r"(a[3]), "r"(b0), "r"(b1));
}

__global__ __launch_bounds__(256, 3) void k_gemm_tc(const float* __restrict__ bias,
                                                    float* __restrict__ out) {
    __shared__ uint32_t As[2][STGW];
    __shared__ uint32_t Bs[2][STGW];

    const int tid  = threadIdx.x;
    const int lane = tid & 31;
    const int warp = tid >> 5;
    const int warp_m = warp & 3;
    const int warp_n = warp >> 2;
    const int g = lane >> 2;
    const int t = lane & 3;

    const int m0 = blockIdx.y * 128;
    const int n0 = blockIdx.x * 128;

    const int ldrow = tid >> 1;        // 0..127
    const int ldcw  = (tid & 1) * 8;   // word offset 0 or 8

    float c[2][8][4];
    #pragma unroll
    for (int i = 0; i < 2; i++)
        #pragma unroll
        for (int j = 0; j < 8; j++)
            #pragma unroll
            for (int r = 0; r < 4; r++) c[i][j][r] = 0.f;

    uint32_t sA = (uint32_t)__cvta_generic_to_shared(&As[0][0]);
    uint32_t sB = (uint32_t)__cvta_generic_to_shared(&Bs[0][0]);

    const uint32_t aoff = ((warp_m * 32 + (lane & 15)) * PITCH + (lane >> 4) * 4) * 4;
    const uint32_t boff = ((warp_n * 64 + (lane & 7) + ((lane >> 4) << 3)) * PITCH
                           + ((lane >> 3) & 1) * 4) * 4;

    const int  m   = m0 + ldrow;
    const bool mok = m < NN;
    const uint32_t* gAr = g_Xt16 + (size_t)(mok ? m : 0) * KW + ldcw;
    const uint32_t* gBr = g_Wt16 + (size_t)(n0 + ldrow) * KW + ldcw;

    auto load_stage = [&](int s, int kkw) {
        uint32_t da = sA + (s * STGW + ldrow * PITCH + ldcw) * 4;
        uint32_t db = sB + (s * STGW + ldrow * PITCH + ldcw) * 4;
        #pragma unroll
        for (int j = 0; j < 2; j++) {
            cpa16(da + j * 16, gAr + kkw + j * 4, mok ? 16 : 0);
            cpa16(db + j * 16, gBr + kkw + j * 4, 16);
        }
    };

    load_stage(0, 0);
    asm volatile("cp.async.commit_group;");

    const int NT = KW / BKW;   // 8 tiles
    for (int it = 0; it < NT; it++) {
        int s = it & 1;
        if (it + 1 < NT) load_stage(s ^ 1, (it + 1) * BKW);
        asm volatile("cp.async.commit_group;");
        asm volatile("cp.async.wait_group 1;");
        __syncthreads();

        uint32_t stA = sA + s * STGW * 4;
        uint32_t stB = sB + s * STGW * 4;
        #pragma unroll
        for (int kt = 0; kt < 2; kt++) {
            const uint32_t kb = kt * 8 * 4;   // byte offset of k16 step
            uint32_t a[2][4];
            #pragma unroll
            for (int mt = 0; mt < 2; mt++)
                ldsm4(a[mt][0], a[mt][1], a[mt][2], a[mt][3],
                      stA + aoff + mt * 16 * PITCH * 4 + kb);
            #pragma unroll
            for (int jp = 0; jp < 4; jp++) {
                uint32_t b0, b1, b2, b3;
                ldsm4(b0, b1, b2, b3, stB + boff + jp * 16 * PITCH * 4 + kb);
                mma16(c[0][2 * jp], a[0], b0, b1);
                mma16(c[1][2 * jp], a[1], b0, b1);
                mma16(c[0][2 * jp + 1], a[0], b2, b3);
                mma16(c[1][2 * jp + 1], a[1], b2, b3);
            }
        }
        __syncthreads();
    }

    #pragma unroll
    for (int nt = 0; nt < 8; nt++) {
        int col = n0 + warp_n * 64 + nt * 8 + 2 * t;
        float bx = bias[col], by = bias[col + 1];
        #pragma unroll
        for (int mt = 0; mt < 2; mt++) {
            int r0 = m0 + warp_m * 32 + mt * 16 + g;
            if (r0 < NN) {
                float2 v = make_float2(fmaxf(c[mt][nt][0] + bx, 0.f),
                                       fmaxf(c[mt][nt][1] + by, 0.f));
                *(float2*)(out + (size_t)r0 * OUTF + col) = v;
            }
            int r1 = r0 + 8;
            if (r1 < NN) {
                float2 v = make_float2(fmaxf(c[mt][nt][2] + bx, 0.f),
                                       fmaxf(c[mt][nt][3] + by, 0.f));
                *(float2*)(out + (size_t)r1 * OUTF + col) = v;
            }
        }
    }
}

extern "C" void kernel_launch(void* const* d_in, const int* in_sizes, int n_in,
                              void* d_out, int out_size) {
    const float* signal = (const float*)d_in[0];
    const int*   src    = (const int*)d_in[1];
    const int*   dst    = (const int*)d_in[2];
    const float* lam    = (const float*)d_in[3];
    const float* W      = (const float*)d_in[4];
    const float* bias   = (const float*)d_in[5];
    float* out = (float*)d_out;

    k_zero<<<(NN + 255) / 256, 256>>>();
    k_deg<<<(NE / 4 + 255) / 256, 256>>>(dst);
    k_scan_part<<<NB, 256>>>();
    k_scan_fill<<<NB, 256>>>();
    k_fill<<<(NE / 8 + 255) / 256, 256>>>(src, dst);
    k_prep<<<(NN * 16 + OUTF * KW + 255) / 256, 256>>>(signal, W);

    // step 1: in = a, out = b; step 2: in = b, out = a; step 3: in = a, out = b
    k_gather_cheb<<<(NN * 16 + 255) / 256, 256>>>(lam, 1, 0);
    k_gather_cheb<<<(NN * 16 + 255) / 256, 256>>>(lam, 2, 1);
    k_gather_cheb<<<(NN * 16 + 255) / 256, 256>>>(lam, 3, 0);

    k_gemm_tc<<<dim3(OUTF / 128, (NN + 127) / 128), 256>>>(bias, out);
}

// round 16
// speedup vs baseline: 1.1057x; 1.1057x over previous
#include <cuda_runtime.h>
#include <cuda_fp16.h>
#include <cstdint>

#define NN 50000
#define NE 800000
#define F 64
#define KF 256    // F * K
#define OUTF 256
#define NB 49     // scan blocks of 1024 nodes
#define KW (KF / 2)   // 128 half2 words per Xt row

// Scratch (device globals: allocation-free rule)
__device__ int   g_degi[NN];
__device__ int   g_rowptr[NN + 1];
__device__ int   g_cursor[NN];
__device__ int   g_csrc[NE];
__device__ int   g_psum[NB];
__device__ __align__(16) float    g_dsqrt[NN];
__device__ __align__(16) uint32_t g_scaled_a[NN * F / 2];   // half2 packed
__device__ __align__(16) uint32_t g_scaled_b[NN * F / 2];
__device__ __align__(16) float    g_Xt[(size_t)NN * KF];    // fp32 recurrence spine
__device__ __align__(16) uint32_t g_Xt16[(size_t)NN * KW];  // half2 words for GEMM A
__device__ __align__(16) uint32_t g_Wt16[OUTF * KW];        // half2, transposed [n][kw]

__global__ void k_zero() {
    int i = blockIdx.x * blockDim.x + threadIdx.x;
    if (i < NN) g_degi[i] = 0;
}

__global__ void k_deg(const int* __restrict__ dst) {
    int e = blockIdx.x * blockDim.x + threadIdx.x;
    if (e < NE) atomicAdd(&g_degi[dst[e]], 1);
}

// ---- parallel scan (2 kernels: partials, then fused top-scan + fill) --------
__global__ __launch_bounds__(256) void k_scan_part() {
    __shared__ int s[256];
    int t = threadIdx.x, b = blockIdx.x;
    int base = b * 1024 + t * 4;
    int sum = 0;
    #pragma unroll
    for (int j = 0; j < 4; j++) {
        int i = base + j;
        if (i < NN) sum += g_degi[i];
    }
    s[t] = sum;
    __syncthreads();
    for (int off = 128; off > 0; off >>= 1) {
        if (t < off) s[t] += s[t + off];
        __syncthreads();
    }
    if (t == 0) g_psum[b] = s[0];
}

__global__ __launch_bounds__(256) void k_scan_fill() {
    __shared__ int s[256];
    __shared__ int tops[64];
    int t = threadIdx.x, b = blockIdx.x;

    if (t < 64) tops[t] = (t < NB) ? g_psum[t] : 0;
    __syncthreads();
    for (int off = 1; off < 64; off <<= 1) {
        int u = (t >= off && t < 64) ? tops[t - off] : 0;
        __syncthreads();
        if (t < 64) tops[t] += u;
        __syncthreads();
    }
    int blockoff = (b == 0) ? 0 : tops[b - 1];
    if (b == 0 && t == 0) g_rowptr[NN] = NE;

    int base = b * 1024 + t * 4;
    int d[4];
    int sum = 0;
    #pragma unroll
    for (int j = 0; j < 4; j++) {
        int i = base + j;
        d[j] = (i < NN) ? g_degi[i] : 0;
        sum += d[j];
    }
    s[t] = sum;
    __syncthreads();
    for (int off = 1; off < 256; off <<= 1) {
        int u = (t >= off) ? s[t - off] : 0;
        __syncthreads();
        s[t] += u;
        __syncthreads();
    }
    int off = blockoff + s[t] - sum;   // exclusive
    #pragma unroll
    for (int j = 0; j < 4; j++) {
        int i = base + j;
        if (i < NN) {
            g_rowptr[i] = off;
            g_cursor[i] = off;
            off += d[j];
        }
    }
}
// -----------------------------------------------------------------------------

// 4 edges per thread: 4 independent ATOMG->STG chains for MLP.
__global__ void k_fill(const int* __restrict__ src, const int* __restrict__ dst) {
    int q = blockIdx.x * blockDim.x + threadIdx.x;     // quad index
    if (q >= NE / 4) return;
    int4 dv = ((const int4*)dst)[q];
    int4 sv = ((const int4*)src)[q];
    int p0 = atomicAdd(&g_cursor[dv.x], 1);
    int p1 = atomicAdd(&g_cursor[dv.y], 1);
    int p2 = atomicAdd(&g_cursor[dv.z], 1);
    int p3 = atomicAdd(&g_cursor[dv.w], 1);
    g_csrc[p0] = sv.x;
    g_csrc[p1] = sv.y;
    g_csrc[p2] = sv.z;
    g_csrc[p3] = sv.w;
}

__device__ __forceinline__ uint32_t pack_h2(float a, float b) {
    __half2 h = __floats2half2_rn(a, b);
    return *(uint32_t*)&h;
}

// Fused prep: node features (d^-1/2, X0 fp32+fp16, scaled fp16) AND W transpose.
__global__ void k_prep(const float* __restrict__ x, const float* __restrict__ W) {
    int t = blockIdx.x * blockDim.x + threadIdx.x;
    if (t < NN * 16) {
        int i = t >> 4, c = t & 15;
        float ds = rsqrtf((float)max(g_degi[i], 1));
        if (c == 0) g_dsqrt[i] = ds;
        float4 v = ((const float4*)x)[(size_t)i * 16 + c];
        ((float4*)(g_Xt + (size_t)i * KF))[c] = v;   // X0 into block 0
        uint2 xw = make_uint2(pack_h2(v.x, v.y), pack_h2(v.z, v.w));
        ((uint2*)(g_Xt16 + (size_t)i * KW))[c] = xw;
        uint2 s = make_uint2(pack_h2(v.x * ds, v.y * ds), pack_h2(v.z * ds, v.w * ds));
        ((uint2*)g_scaled_a)[(size_t)i * 16 + c] = s;
    } else {
        int i = t - NN * 16;
        if (i < OUTF * KW) {
            int n = i / KW, w = i % KW;
            int k = 2 * w;
            g_Wt16[(size_t)n * KW + w] =
                pack_h2(W[(size_t)k * OUTF + n], W[(size_t)(k + 1) * OUTF + n]);
        }
    }
}

// Gather-based Laplacian (fp16 inputs, fp32 math) + fused Chebyshev recurrence.
// Step 3 skips the fp32 Xt write and the scaled-output write (dead stores:
// nothing downstream reads X3 in fp32, and there is no step 4).
__global__ __launch_bounds__(256) void k_gather_cheb(const float* __restrict__ lambda_max,
                                                     int step, int ping) {
    int t = blockIdx.x * blockDim.x + threadIdx.x;
    if (t >= NN * 16) return;
    int i = t >> 4, c = t & 15;
    const uint2* in = (const uint2*)(ping ? g_scaled_b : g_scaled_a);
    uint2* outb = (uint2*)(ping ? g_scaled_a : g_scaled_b);

    int lo = g_rowptr[i], hi = g_rowptr[i + 1];
    float4 a0 = make_float4(0.f, 0.f, 0.f, 0.f);
    float4 a1 = make_float4(0.f, 0.f, 0.f, 0.f);
    float4 a2 = make_float4(0.f, 0.f, 0.f, 0.f);
    float4 a3 = make_float4(0.f, 0.f, 0.f, 0.f);

    auto acc = [&](float4& a, uint2 v) {
        float2 lo2 = __half22float2(*(__half2*)&v.x);
        float2 hi2 = __half22float2(*(__half2*)&v.y);
        a.x += lo2.x; a.y += lo2.y; a.z += hi2.x; a.w += hi2.y;
    };

    int j = lo;
    for (; j + 3 < hi; j += 4) {
        int s0 = __ldg(&g_csrc[j]);
        int s1 = __ldg(&g_csrc[j + 1]);
        int s2 = __ldg(&g_csrc[j + 2]);
        int s3 = __ldg(&g_csrc[j + 3]);
        uint2 v0 = in[(size_t)s0 * 16 + c];
        uint2 v1 = in[(size_t)s1 * 16 + c];
        uint2 v2 = in[(size_t)s2 * 16 + c];
        uint2 v3 = in[(size_t)s3 * 16 + c];
        acc(a0, v0); acc(a1, v1); acc(a2, v2); acc(a3, v3);
    }
    for (; j < hi; j++) {
        int s0 = __ldg(&g_csrc[j]);
        acc(a0, in[(size_t)s0 * 16 + c]);
    }
    float ds = g_dsqrt[i];
    float4 L = make_float4((a0.x + a1.x + a2.x + a3.x) * ds,
                           (a0.y + a1.y + a2.y + a3.y) * ds,
                           (a0.z + a1.z + a2.z + a3.z) * ds,
                           (a0.w + a1.w + a2.w + a3.w) * ds);

    float rn = 2.0f / lambda_max[0];
    float4* XtRow = (float4*)(g_Xt + (size_t)i * KF);
    float4 xp = XtRow[(step - 1) * 16 + c];
    float4 xn;
    if (step == 1) {
        float cL = -rn, cP = rn - 1.0f;
        xn = make_float4(cL * L.x + cP * xp.x, cL * L.y + cP * xp.y,
                         cL * L.z + cP * xp.z, cL * L.w + cP * xp.w);
    } else {
        float4 xpp = XtRow[(step - 2) * 16 + c];
        float cL = -2.0f * rn, cP = 2.0f * (rn - 1.0f);
        xn = make_float4(cL * L.x + cP * xp.x - xpp.x, cL * L.y + cP * xp.y - xpp.y,
                         cL * L.z + cP * xp.z - xpp.z, cL * L.w + cP * xp.w - xpp.w);
    }
    uint2 xw = make_uint2(pack_h2(xn.x, xn.y), pack_h2(xn.z, xn.w));
    ((uint2*)(g_Xt16 + (size_t)i * KW))[step * 16 + c] = xw;
    if (step < 3) {
        XtRow[step * 16 + c] = xn;
        uint2 s = make_uint2(pack_h2(xn.x * ds, xn.y * ds), pack_h2(xn.z * ds, xn.w * ds));
        outb[(size_t)i * 16 + c] = s;
    }
}

// ---------------------------------------------------------------------------
// FP16 tensor-core GEMM with ldmatrix fragment loads (R11 config: 123.4us).
// 128x128 block tile, BKW=16 half2-words per stage, 2-stage cp.async,
// static 40KB smem, 256 threads (8 warps, 4x2), warp tile 32x64,
// mma.sync.m16n8k16.f16. PITCH 20: conflict-free for both LDSM and cp.async.
// ---------------------------------------------------------------------------
#define BKW 16
#define PITCH 20
#define STGW (128 * PITCH)   // words per stage

__device__ __forceinline__ void cpa16(uint32_t dst_smem, const void* src, int sz) {
    asm volatile("cp.async.cg.shared.global [%0], [%1], 16, %2;"
                 :: "r"(dst_smem), "l"(src), "r"(sz));
}

__device__ __forceinline__ void ldsm4(uint32_t& r0, uint32_t& r1, uint32_t& r2,
                                      uint32_t& r3, uint32_t addr) {
    asm volatile("ldmatrix.sync.aligned.m8n8.x4.shared.b16 {%0,%1,%2,%3}, [%4];"
                 : "=r"(r0), "=r"(r1), "=r"(r2), "=r"(r3) : "r"(addr));
}

__global__ __launch_bounds__(256) void k_gemm_tc(const float* __restrict__ bias,
                                                 float* __restrict__ out) {
    __shared__ uint32_t As[2][STGW];
    __shared__ uint32_t Bs[2][STGW];

    const int tid  = threadIdx.x;
    const int lane = tid & 31;
    const int warp = tid >> 5;
    const int warp_m = warp & 3;
    const int warp_n = warp >> 2;
    const int g = lane >> 2;
    const int t = lane & 3;

    const int m0 = blockIdx.y * 128;
    const int n0 = blockIdx.x * 128;

    // loader: 2 threads per row, each 8 words (2x 16B cp.async)
    const int ldrow = tid >> 1;        // 0..127
    const int ldcw  = (tid & 1) * 8;   // word offset 0 or 8

    float c[2][8][4];
    #pragma unroll
    for (int i = 0; i < 2; i++)
        #pragma unroll
        for (int j = 0; j < 8; j++)
            #pragma unroll
            for (int r = 0; r < 4; r++) c[i][j][r] = 0.f;

    uint32_t sA = (uint32_t)__cvta_generic_to_shared(&As[0][0]);
    uint32_t sB = (uint32_t)__cvta_generic_to_shared(&Bs[0][0]);

    // ldmatrix lane addresses (byte offsets within a stage)
    const uint32_t aoff = ((warp_m * 32 + (lane & 15)) * PITCH + (lane >> 4) * 4) * 4;
    const uint32_t boff = ((warp_n * 64 + (lane & 7) + ((lane >> 4) << 3)) * PITCH
                           + ((lane >> 3) & 1) * 4) * 4;

    const int  m   = m0 + ldrow;
    const bool mok = m < NN;
    const uint32_t* gAr = g_Xt16 + (size_t)(mok ? m : 0) * KW + ldcw;
    const uint32_t* gBr = g_Wt16 + (size_t)(n0 + ldrow) * KW + ldcw;

    auto load_stage = [&](int s, int kkw) {
        uint32_t da = sA + (s * STGW + ldrow * PITCH + ldcw) * 4;
        uint32_t db = sB + (s * STGW + ldrow * PITCH + ldcw) * 4;
        #pragma unroll
        for (int j = 0; j < 2; j++) {
            cpa16(da + j * 16, gAr + kkw + j * 4, mok ? 16 : 0);
            cpa16(db + j * 16, gBr + kkw + j * 4, 16);
        }
    };

    load_stage(0, 0);
    asm volatile("cp.async.commit_group;");

    const int NT = KW / BKW;   // 8 tiles
    for (int it = 0; it < NT; it++) {
        int s = it & 1;
        if (it + 1 < NT) load_stage(s ^ 1, (it + 1) * BKW);
        asm volatile("cp.async.commit_group;");
        asm volatile("cp.async.wait_group 1;");
        __syncthreads();

        uint32_t stA = sA + s * STGW * 4;
        uint32_t stB = sB + s * STGW * 4;
        #pragma unroll
        for (int kt = 0; kt < 2; kt++) {
            const uint32_t kb = kt * 8 * 4;   // byte offset of k16 step (8 words)
            uint32_t a[2][4], b[8][2];
            #pragma unroll
            for (int mt = 0; mt < 2; mt++)
                ldsm4(a[mt][0], a[mt][1], a[mt][2], a[mt][3],
                      stA + aoff + mt * 16 * PITCH * 4 + kb);
            #pragma unroll
            for (int j = 0; j < 4; j++)
                ldsm4(b[2 * j][0], b[2 * j][1], b[2 * j + 1][0], b[2 * j + 1][1],
                      stB + boff + j * 16 * PITCH * 4 + kb);
            #pragma unroll
            for (int mt = 0; mt < 2; mt++)
                #pragma unroll
                for (int nt = 0; nt < 8; nt++) {
                    asm volatile(
                        "mma.sync.aligned.m16n8k16.row.col.f32.f16.f16.f32 "
                        "{%0,%1,%2,%3}, {%4,%5,%6,%7}, {%8,%9}, {%0,%1,%2,%3};"
                        : "+f"(c[mt][nt][0]), "+f"(c[mt][nt][1]),
                          "+f"(c[mt][nt][2]), "+f"(c[mt][nt][3])
                        : "r"(a[mt][0]), "r"(a[mt][1]), "r"(a[mt][2]), "r"(a[mt][3]),
                          "r"(b[nt][0]), "r"(b[nt][1]));
                }
        }
        __syncthreads();
    }

    #pragma unroll
    for (int nt = 0; nt < 8; nt++) {
        int col = n0 + warp_n * 64 + nt * 8 + 2 * t;
        float bx = bias[col], by = bias[col + 1];
        #pragma unroll
        for (int mt = 0; mt < 2; mt++) {
            int r0 = m0 + warp_m * 32 + mt * 16 + g;
            if (r0 < NN) {
                float2 v = make_float2(fmaxf(c[mt][nt][0] + bx, 0.f),
                                       fmaxf(c[mt][nt][1] + by, 0.f));
                *(float2*)(out + (size_t)r0 * OUTF + col) = v;
            }
            int r1 = r0 + 8;
            if (r1 < NN) {
                float2 v = make_float2(fmaxf(c[mt][nt][2] + bx, 0.f),
                                       fmaxf(c[mt][nt][3] + by, 0.f));
                *(float2*)(out + (size_t)r1 * OUTF + col) = v;
            }
        }
    }
}

extern "C" void kernel_launch(void* const* d_in, const int* in_sizes, int n_in,
                              void* d_out, int out_size) {
    const float* signal = (const float*)d_in[0];
    const int*   src    = (const int*)d_in[1];
    const int*   dst    = (const int*)d_in[2];
    const float* lam    = (const float*)d_in[3];
    const float* W      = (const float*)d_in[4];
    const float* bias   = (const float*)d_in[5];
    float* out = (float*)d_out;

    k_zero<<<(NN + 255) / 256, 256>>>();
    k_deg<<<(NE + 255) / 256, 256>>>(dst);
    k_scan_part<<<NB, 256>>>();
    k_scan_fill<<<NB, 256>>>();
    k_fill<<<(NE / 4 + 255) / 256, 256>>>(src, dst);
    k_prep<<<(NN * 16 + OUTF * KW + 255) / 256, 256>>>(signal, W);

    // step 1: in = a, out = b; step 2: in = b, out = a; step 3: in = a, out = b
    k_gather_cheb<<<(NN * 16 + 255) / 256, 256>>>(lam, 1, 0);
    k_gather_cheb<<<(NN * 16 + 255) / 256, 256>>>(lam, 2, 1);
    k_gather_cheb<<<(NN * 16 + 255) / 256, 256>>>(lam, 3, 0);

    k_gemm_tc<<<dim3(OUTF / 128, (NN + 127) / 128), 256>>>(bias, out);
}